// round 13
// baseline (speedup 1.0000x reference)
#include <cuda_runtime.h>
#include <cuda_fp16.h>
#include <cstdint>

#define S_LEN 2048
#define B_SZ  2
#define D_MOD 1024
#define H_NUM 16
#define DH_SZ 64
#define WIN_SZ 256
#define M_ROWS (S_LEN * B_SZ)   // 4096

// Scratch (device globals — no allocation allowed)
__device__ __half g_h_X[M_ROWS * D_MOD];         // fp16 x
__device__ __half g_h_WT[4 * D_MOD * D_MOD];     // fp16 W^T (q,k,v,o) [n][k]
__device__ __half g_h_Q[M_ROWS * D_MOD];
__device__ __half g_h_K[M_ROWS * D_MOD];
__device__ __half g_h_V[M_ROWS * D_MOD];
__device__ __half g_h_O[M_ROWS * D_MOD];

// ---------------------------------------------------------------------------
__device__ __forceinline__ void cp16(uint32_t dst_smem, const void* src) {
    asm volatile("cp.async.cg.shared.global [%0], [%1], 16;"
                 :: "r"(dst_smem), "l"(src));
}
__device__ __forceinline__ void ldsm4(uint32_t& r0, uint32_t& r1, uint32_t& r2,
                                      uint32_t& r3, uint32_t addr) {
    asm volatile("ldmatrix.sync.aligned.m8n8.x4.shared.b16 {%0,%1,%2,%3}, [%4];"
                 : "=r"(r0), "=r"(r1), "=r"(r2), "=r"(r3) : "r"(addr));
}
__device__ __forceinline__ void ldsm4t(uint32_t& r0, uint32_t& r1, uint32_t& r2,
                                       uint32_t& r3, uint32_t addr) {
    asm volatile("ldmatrix.sync.aligned.m8n8.x4.trans.shared.b16 {%0,%1,%2,%3}, [%4];"
                 : "=r"(r0), "=r"(r1), "=r"(r2), "=r"(r3) : "r"(addr));
}
__device__ __forceinline__ void mma_f16(float c[4], const uint32_t a[4],
                                        const uint32_t b0, const uint32_t b1) {
    asm volatile(
        "mma.sync.aligned.m16n8k16.row.col.f32.f16.f16.f32 "
        "{%0,%1,%2,%3}, {%4,%5,%6,%7}, {%8,%9}, {%0,%1,%2,%3};"
        : "+f"(c[0]), "+f"(c[1]), "+f"(c[2]), "+f"(c[3])
        : "r"(a[0]), "r"(a[1]), "r"(a[2]), "r"(a[3]), "r"(b0), "r"(b1));
}

// ---------------------------------------------------------------------------
// merged pre-pass: z<4 -> transpose+round W_z into WT[n][k]; z==4 -> round x
// ---------------------------------------------------------------------------
__global__ void swa_prep(const float* __restrict__ x,
                         const float* __restrict__ Wq, const float* __restrict__ Wk,
                         const float* __restrict__ Wv, const float* __restrict__ Wo,
                         __half* __restrict__ XH, __half* __restrict__ WT) {
    const int z = blockIdx.z;
    if (z < 4) {
        __shared__ float t[32][33];
        const float* W = (z == 0) ? Wq : (z == 1) ? Wk : (z == 2) ? Wv : Wo;
        __half* Dst = WT + (size_t)z * D_MOD * D_MOD;
        const int n0 = blockIdx.x * 32, k0 = blockIdx.y * 32;
#pragma unroll
        for (int i = threadIdx.y; i < 32; i += 8)
            t[i][threadIdx.x] = W[(size_t)(k0 + i) * D_MOD + n0 + threadIdx.x];
        __syncthreads();
#pragma unroll
        for (int i = threadIdx.y; i < 32; i += 8)
            Dst[(size_t)(n0 + i) * D_MOD + k0 + threadIdx.x] =
                __float2half_rn(t[threadIdx.x][i]);
    } else {
        const int blk = blockIdx.y * 32 + blockIdx.x;
        const int tid = threadIdx.y * 32 + threadIdx.x;
        const float4* xin = (const float4*)x;
        __half2* xout = (__half2*)XH;
#pragma unroll
        for (int i = 0; i < 4; ++i) {
            const int f4 = blk * 1024 + tid + i * 256;
            float4 v = xin[f4];
            xout[2 * f4 + 0] = __floats2half2_rn(v.x, v.y);
            xout[2 * f4 + 1] = __floats2half2_rn(v.z, v.w);
        }
    }
}

// ---------------------------------------------------------------------------
// fp16 mma.sync GEMM: C = A[m][k] @ WT[n][k]^T + bias.
// 128x128x64 tiles, 256 thr, 8 warps (64x32), 3-stage cp.async ring,
// ONE __syncthreads per k-chunk. Row pitch 144 B.
// smem: 3 stages x (A 18432 + B 18432) = 110592 B -> occupancy 2.
// ---------------------------------------------------------------------------
#define GSTAGE 36864
#define GEMM_SMEM (3 * GSTAGE)

template <bool STORE_HALF, typename OutT>
__device__ __forceinline__
void gemm_body(const __half* __restrict__ A, const __half* __restrict__ B,
               const float* __restrict__ bias, OutT* __restrict__ C) {
    extern __shared__ char smc[];
    const uint32_t smb = (uint32_t)__cvta_generic_to_shared(smc);
    const int tid  = threadIdx.x;
    const int lane = tid & 31;
    const int warp = tid >> 5;
    const int wr   = warp & 1;          // m 64*wr
    const int wc   = warp >> 1;         // n 32*wc
    const int m0   = blockIdx.y * 128;
    const int n0   = blockIdx.x * 128;

    const __half* Ab = A + (size_t)m0 * 1024;
    const __half* Bb = B + (size_t)n0 * 1024;

    const int mat = lane >> 3, lr = lane & 7;
    uint32_t aOff[4];
#pragma unroll
    for (int mt = 0; mt < 4; ++mt)
        aOff[mt] = (uint32_t)((wr * 64 + mt * 16 + (mat & 1) * 8 + lr) * 144 + (mat >> 1) * 16);
    uint32_t bOff[2];
#pragma unroll
    for (int p = 0; p < 2; ++p)
        bOff[p] = (uint32_t)((wc * 32 + p * 16 + (mat >> 1) * 8 + lr) * 144 + (mat & 1) * 16)
                  + 18432u;   // B half of each stage

    float acc[4][4][4];
#pragma unroll
    for (int mt = 0; mt < 4; ++mt)
#pragma unroll
        for (int nt = 0; nt < 4; ++nt)
#pragma unroll
            for (int i = 0; i < 4; ++i) acc[mt][nt][i] = 0.0f;

    const int srow = tid & 127;          // staged row
    const int sop  = tid >> 7;           // 0 = A, 1 = B
    auto stage = [&](int kc) {
        const uint32_t base = smb + (uint32_t)(kc % 3) * GSTAGE + (sop ? 18432u : 0u);
        const __half* g = (sop ? Bb : Ab) + (size_t)srow * 1024 + kc * 64;
        const uint32_t d = base + (uint32_t)srow * 144;
#pragma unroll
        for (int c = 0; c < 8; ++c)
            cp16(d + c * 16, g + c * 8);
    };

    stage(0);
    asm volatile("cp.async.commit_group;");
    stage(1);
    asm volatile("cp.async.commit_group;");

    const int NIT = 1024 / 64;  // 16
    for (int kc = 0; kc < NIT; ++kc) {
        if (kc + 1 < NIT) {
            asm volatile("cp.async.wait_group 1;");
        } else {
            asm volatile("cp.async.wait_group 0;");
        }
        __syncthreads();   // chunk kc visible to all; buf (kc-1)%3 free

        if (kc + 2 < NIT) {
            stage(kc + 2);
            asm volatile("cp.async.commit_group;");
        }

        const uint32_t sb = smb + (uint32_t)(kc % 3) * GSTAGE;
#pragma unroll
        for (int s = 0; s < 4; ++s) {
            const uint32_t kb = (uint32_t)(s * 32);
            uint32_t af[4][4], bf[2][4];
#pragma unroll
            for (int mt = 0; mt < 4; ++mt)
                ldsm4(af[mt][0], af[mt][1], af[mt][2], af[mt][3], sb + aOff[mt] + kb);
#pragma unroll
            for (int p = 0; p < 2; ++p)
                ldsm4(bf[p][0], bf[p][1], bf[p][2], bf[p][3], sb + bOff[p] + kb);
#pragma unroll
            for (int mt = 0; mt < 4; ++mt)
#pragma unroll
                for (int p = 0; p < 2; ++p) {
                    mma_f16(acc[mt][2 * p + 0], af[mt], bf[p][0], bf[p][1]);
                    mma_f16(acc[mt][2 * p + 1], af[mt], bf[p][2], bf[p][3]);
                }
        }
    }

    // epilogue
#pragma unroll
    for (int mt = 0; mt < 4; ++mt) {
        const int row = m0 + wr * 64 + mt * 16 + (lane >> 2);
#pragma unroll
        for (int nt = 0; nt < 4; ++nt) {
            const int col = n0 + wc * 32 + nt * 8 + 2 * (lane & 3);
            const float2 bia = *(const float2*)&bias[col];
            const float x0 = acc[mt][nt][0] + bia.x;
            const float y0 = acc[mt][nt][1] + bia.y;
            const float x1 = acc[mt][nt][2] + bia.x;
            const float y1 = acc[mt][nt][3] + bia.y;
            if (STORE_HALF) {
                __half2* Ch = (__half2*)C;
                Ch[((size_t)row * 1024 + col) >> 1]       = __floats2half2_rn(x0, y0);
                Ch[((size_t)(row + 8) * 1024 + col) >> 1] = __floats2half2_rn(x1, y1);
            } else {
                float* Cf = (float*)C;
                *(float2*)&Cf[(size_t)row * 1024 + col]       = make_float2(x0, y0);
                *(float2*)&Cf[(size_t)(row + 8) * 1024 + col] = make_float2(x1, y1);
            }
        }
    }
}

__global__ __launch_bounds__(256, 2)
void swa_gemm_qkv(const __half* __restrict__ xh, const __half* __restrict__ WT,
                  const float* __restrict__ bq, const float* __restrict__ bk,
                  const float* __restrict__ bv,
                  __half* __restrict__ Q, __half* __restrict__ K, __half* __restrict__ V) {
    const int z = blockIdx.z;
    const __half* W = WT + (size_t)z * D_MOD * D_MOD;
    const float* bias = (z == 0) ? bq : (z == 1) ? bk : bv;
    __half* C = (z == 0) ? Q : (z == 1) ? K : V;
    gemm_body<true>(xh, W, bias, C);
}

__global__ __launch_bounds__(256, 2)
void swa_gemm_o(const __half* __restrict__ A, const __half* __restrict__ WT,
                const float* __restrict__ bias, float* __restrict__ C) {
    gemm_body<false>(A, WT + (size_t)3 * D_MOD * D_MOD, bias, C);
}

// ---------------------------------------------------------------------------
// Attention v5 (fp16) — unchanged (R8).
// smem halves (pitch 144 B): Qs@0  Ks@9216B  Vs@18432B  Ps@27648B ; 36864 B.
// ---------------------------------------------------------------------------
#define A5_KS 9216
#define A5_VS 18432
#define A5_PS 27648
#define ATTN5_SMEM 36864

__global__ __launch_bounds__(128, 3)
void swa_attn5(const __half* __restrict__ Q, const __half* __restrict__ K,
               const __half* __restrict__ V, const float* __restrict__ beta,
               __half* __restrict__ O) {
    extern __shared__ char smc[];
    const uint32_t smb  = (uint32_t)__cvta_generic_to_shared(smc);
    __half* Ps = (__half*)(smc + A5_PS);

    const int z  = blockIdx.y;
    const int b  = z / H_NUM;
    const int h  = z % H_NUM;
    const int q0 = blockIdx.x * 64;
    const int tid  = threadIdx.x;
    const int lane = tid & 31;
    const int warp = tid >> 5;
    const int g   = lane >> 2;
    const int t4  = lane & 3;
    const int mat = lane >> 3, lr = lane & 7;

    const float scale = 1.0f / (8.0f * __expf(beta[h]));

#pragma unroll
    for (int it = 0; it < 4; ++it) {
        const int f = tid + it * 128;
        const int row = f >> 3, c = f & 7;
        cp16(smb + (uint32_t)(row * 144 + c * 16),
             Q + ((size_t)((q0 + row) * B_SZ + b)) * D_MOD + h * DH_SZ + c * 8);
    }
    asm volatile("cp.async.commit_group;");
    asm volatile("cp.async.wait_group 0;");
    __syncthreads();

    const uint32_t aRow = (uint32_t)((16 * warp + (mat & 1) * 8 + lr) * 144 + (mat >> 1) * 16);
    uint32_t qa[4][4];
#pragma unroll
    for (int s = 0; s < 4; ++s)
        ldsm4(qa[s][0], qa[s][1], qa[s][2], qa[s][3], smb + aRow + s * 32);

    uint32_t kOff[4];
#pragma unroll
    for (int p = 0; p < 4; ++p)
        kOff[p] = (uint32_t)((p * 16 + (mat >> 1) * 8 + lr) * 144 + (mat & 1) * 16);
    uint32_t vRowB[4];
#pragma unroll
    for (int s = 0; s < 4; ++s)
        vRowB[s] = (uint32_t)((s * 16 + (mat & 1) * 8 + lr) * 144 + (mat >> 1) * 16);

    float acc[8][4];
#pragma unroll
    for (int j = 0; j < 8; ++j)
#pragma unroll
        for (int i = 0; i < 4; ++i) acc[j][i] = 0.0f;

    const int r0  = 16 * warp + g;
    const int qr0 = q0 + r0;
    const int qr1 = qr0 + 8;
    float m0 = 0.0f, m1 = 0.0f, l0 = 1.0f, l1 = 1.0f;

    int kbeg = q0 - (WIN_SZ - 1);
    if (kbeg < 0) kbeg = 0;
    kbeg &= ~63;

    for (int t = kbeg; t < q0 + 64; t += 64) {
#pragma unroll
        for (int it = 0; it < 4; ++it) {
            const int f = tid + it * 128;
            const int row = f >> 3, c = f & 7;
            const size_t gofs = ((size_t)((t + row) * B_SZ + b)) * D_MOD + h * DH_SZ + c * 8;
            cp16(smb + A5_KS + (uint32_t)(row * 144 + c * 16), K + gofs);
            cp16(smb + A5_VS + (uint32_t)(row * 144 + c * 16), V + gofs);
        }
        asm volatile("cp.async.commit_group;");
        asm volatile("cp.async.wait_group 0;");
        __syncthreads();

        float c[8][4];
#pragma unroll
        for (int j = 0; j < 8; ++j)
#pragma unroll
            for (int i = 0; i < 4; ++i) c[j][i] = 0.0f;

#pragma unroll
        for (int s = 0; s < 4; ++s) {
            const uint32_t kb = (uint32_t)(s * 32);
#pragma unroll
            for (int p = 0; p < 4; ++p) {
                uint32_t b0, b1, b2, b3;
                ldsm4(b0, b1, b2, b3, smb + A5_KS + kOff[p] + kb);
                mma_f16(c[2 * p + 0], qa[s], b0, b1);
                mma_f16(c[2 * p + 1], qa[s], b2, b3);
            }
        }

#pragma unroll
        for (int j = 0; j < 8; ++j) {
            const int k0i = t + j * 8 + 2 * t4;
#pragma unroll
            for (int u = 0; u < 2; ++u) {
                const int kidx = k0i + u;
                const int d0q = qr0 - kidx;
                const int d1q = qr1 - kidx;
                c[j][u]     = (d0q >= 0 && d0q < WIN_SZ) ? c[j][u] * scale     : -1e30f;
                c[j][2 + u] = (d1q >= 0 && d1q < WIN_SZ) ? c[j][2 + u] * scale : -1e30f;
            }
        }

        float mx0 = m0, mx1 = m1;
#pragma unroll
        for (int j = 0; j < 8; ++j) {
            mx0 = fmaxf(mx0, fmaxf(c[j][0], c[j][1]));
            mx1 = fmaxf(mx1, fmaxf(c[j][2], c[j][3]));
        }
        mx0 = fmaxf(mx0, __shfl_xor_sync(0xffffffffu, mx0, 1));
        mx0 = fmaxf(mx0, __shfl_xor_sync(0xffffffffu, mx0, 2));
        mx1 = fmaxf(mx1, __shfl_xor_sync(0xffffffffu, mx1, 1));
        mx1 = fmaxf(mx1, __shfl_xor_sync(0xffffffffu, mx1, 2));

        const float fs0 = __expf(m0 - mx0);
        const float fs1 = __expf(m1 - mx1);
        float s0 = 0.0f, s1 = 0.0f;
#pragma unroll
        for (int j = 0; j < 8; ++j) {
            const float p0 = __expf(c[j][0] - mx0);
            const float p1 = __expf(c[j][1] - mx0);
            const float p2 = __expf(c[j][2] - mx1);
            const float p3 = __expf(c[j][3] - mx1);
            s0 += p0 + p1;
            s1 += p2 + p3;
            *(__half2*)&Ps[r0 * 72 + j * 8 + 2 * t4]       = __floats2half2_rn(p0, p1);
            *(__half2*)&Ps[(r0 + 8) * 72 + j * 8 + 2 * t4] = __floats2half2_rn(p2, p3);
        }
        s0 += __shfl_xor_sync(0xffffffffu, s0, 1);
        s0 += __shfl_xor_sync(0xffffffffu, s0, 2);
        s1 += __shfl_xor_sync(0xffffffffu, s1, 1);
        s1 += __shfl_xor_sync(0xffffffffu, s1, 2);

        l0 = l0 * fs0 + s0;
        l1 = l1 * fs1 + s1;
        m0 = mx0; m1 = mx1;

#pragma unroll
        for (int j = 0; j < 8; ++j) {
            acc[j][0] *= fs0; acc[j][1] *= fs0;
            acc[j][2] *= fs1; acc[j][3] *= fs1;
        }
        __syncwarp();

#pragma unroll
        for (int s = 0; s < 4; ++s) {
            uint32_t pa[4];
            ldsm4(pa[0], pa[1], pa[2], pa[3], smb + A5_PS + aRow + s * 32);
#pragma unroll
            for (int p = 0; p < 4; ++p) {
                uint32_t v0, v1, v2, v3;
                ldsm4t(v0, v1, v2, v3, smb + A5_VS + vRowB[s] + p * 32);
                mma_f16(acc[2 * p + 0], pa, v0, v1);
                mma_f16(acc[2 * p + 1], pa, v2, v3);
            }
        }
        __syncthreads();
    }

    const float rl0 = 1.0f / l0;
    const float rl1 = 1.0f / l1;
#pragma unroll
    for (int j = 0; j < 8; ++j) {
        const int col = h * DH_SZ + j * 8 + 2 * t4;
        *(__half2*)&O[((size_t)(qr0 * B_SZ + b)) * D_MOD + col] =
            __floats2half2_rn(acc[j][0] * rl0, acc[j][1] * rl0);
        *(__half2*)&O[((size_t)(qr1 * B_SZ + b)) * D_MOD + col] =
            __floats2half2_rn(acc[j][2] * rl1, acc[j][3] * rl1);
    }
}

// ---------------------------------------------------------------------------
extern "C" void kernel_launch(void* const* d_in, const int* in_sizes, int n_in,
                              void* d_out, int out_size) {
    const float* x    = (const float*)d_in[0];
    const float* beta = (const float*)d_in[1];
    const float* Wq   = (const float*)d_in[2];
    const float* bq   = (const float*)d_in[3];
    const float* Wk   = (const float*)d_in[4];
    const float* bk   = (const float*)d_in[5];
    const float* Wv   = (const float*)d_in[6];
    const float* bv   = (const float*)d_in[7];
    const float* Wo   = (const float*)d_in[8];
    const float* bo   = (const float*)d_in[9];
    float* out = (float*)d_out;

    __half *XH, *WTH, *Qh, *Kh, *Vh, *Oh;
    cudaGetSymbolAddress((void**)&XH,  g_h_X);
    cudaGetSymbolAddress((void**)&WTH, g_h_WT);
    cudaGetSymbolAddress((void**)&Qh,  g_h_Q);
    cudaGetSymbolAddress((void**)&Kh,  g_h_K);
    cudaGetSymbolAddress((void**)&Vh,  g_h_V);
    cudaGetSymbolAddress((void**)&Oh,  g_h_O);

    cudaFuncSetAttribute(swa_attn5, cudaFuncAttributeMaxDynamicSharedMemorySize,
                         ATTN5_SMEM);
    cudaFuncSetAttribute(swa_gemm_qkv, cudaFuncAttributeMaxDynamicSharedMemorySize,
                         GEMM_SMEM);
    cudaFuncSetAttribute(swa_gemm_o, cudaFuncAttributeMaxDynamicSharedMemorySize,
                         GEMM_SMEM);

    swa_prep<<<dim3(32, 32, 5), dim3(32, 8)>>>(x, Wq, Wk, Wv, Wo, XH, WTH);

    dim3 qkvgrid(D_MOD / 128, M_ROWS / 128, 3);   // (8, 32, 3)
    swa_gemm_qkv<<<qkvgrid, 256, GEMM_SMEM>>>(XH, WTH, bq, bk, bv, Qh, Kh, Vh);

    dim3 agrid(S_LEN / 64, B_SZ * H_NUM);         // (32, 32)
    swa_attn5<<<agrid, 128, ATTN5_SMEM>>>(Qh, Kh, Vh, beta, Oh);

    dim3 ogrid(D_MOD / 128, M_ROWS / 128);        // (8, 32)
    swa_gemm_o<<<ogrid, 256, GEMM_SMEM>>>(Oh, WTH, bo, out);
}

// round 14
// speedup vs baseline: 1.0004x; 1.0004x over previous
#include <cuda_runtime.h>
#include <cuda_fp16.h>
#include <cstdint>

#define S_LEN 2048
#define B_SZ  2
#define D_MOD 1024
#define H_NUM 16
#define DH_SZ 64
#define WIN_SZ 256
#define M_ROWS (S_LEN * B_SZ)   // 4096

// Scratch (device globals — no allocation allowed)
__device__ __half g_h_X[M_ROWS * D_MOD];         // fp16 x
__device__ __half g_h_WT[4 * D_MOD * D_MOD];     // fp16 W^T (q,k,v,o) [n][k]
__device__ __half g_h_Q[M_ROWS * D_MOD];
__device__ __half g_h_K[M_ROWS * D_MOD];
__device__ __half g_h_V[M_ROWS * D_MOD];
__device__ __half g_h_O[M_ROWS * D_MOD];

// ---------------------------------------------------------------------------
__device__ __forceinline__ void cp16(uint32_t dst_smem, const void* src) {
    asm volatile("cp.async.cg.shared.global [%0], [%1], 16;"
                 :: "r"(dst_smem), "l"(src));
}
__device__ __forceinline__ void ldsm4(uint32_t& r0, uint32_t& r1, uint32_t& r2,
                                      uint32_t& r3, uint32_t addr) {
    asm volatile("ldmatrix.sync.aligned.m8n8.x4.shared.b16 {%0,%1,%2,%3}, [%4];"
                 : "=r"(r0), "=r"(r1), "=r"(r2), "=r"(r3) : "r"(addr));
}
__device__ __forceinline__ void ldsm4t(uint32_t& r0, uint32_t& r1, uint32_t& r2,
                                       uint32_t& r3, uint32_t addr) {
    asm volatile("ldmatrix.sync.aligned.m8n8.x4.trans.shared.b16 {%0,%1,%2,%3}, [%4];"
                 : "=r"(r0), "=r"(r1), "=r"(r2), "=r"(r3) : "r"(addr));
}
__device__ __forceinline__ void mma_f16(float c[4], const uint32_t a[4],
                                        const uint32_t b0, const uint32_t b1) {
    asm volatile(
        "mma.sync.aligned.m16n8k16.row.col.f32.f16.f16.f32 "
        "{%0,%1,%2,%3}, {%4,%5,%6,%7}, {%8,%9}, {%0,%1,%2,%3};"
        : "+f"(c[0]), "+f"(c[1]), "+f"(c[2]), "+f"(c[3])
        : "r"(a[0]), "r"(a[1]), "r"(a[2]), "r"(a[3]), "r"(b0), "r"(b1));
}

// ---------------------------------------------------------------------------
// merged pre-pass: z<4 -> transpose+round W_z into WT[n][k]; z==4 -> round x
// ---------------------------------------------------------------------------
__global__ void swa_prep(const float* __restrict__ x,
                         const float* __restrict__ Wq, const float* __restrict__ Wk,
                         const float* __restrict__ Wv, const float* __restrict__ Wo,
                         __half* __restrict__ XH, __half* __restrict__ WT) {
    const int z = blockIdx.z;
    if (z < 4) {
        __shared__ float t[32][33];
        const float* W = (z == 0) ? Wq : (z == 1) ? Wk : (z == 2) ? Wv : Wo;
        __half* Dst = WT + (size_t)z * D_MOD * D_MOD;
        const int n0 = blockIdx.x * 32, k0 = blockIdx.y * 32;
#pragma unroll
        for (int i = threadIdx.y; i < 32; i += 8)
            t[i][threadIdx.x] = W[(size_t)(k0 + i) * D_MOD + n0 + threadIdx.x];
        __syncthreads();
#pragma unroll
        for (int i = threadIdx.y; i < 32; i += 8)
            Dst[(size_t)(n0 + i) * D_MOD + k0 + threadIdx.x] =
                __float2half_rn(t[threadIdx.x][i]);
    } else {
        const int blk = blockIdx.y * 32 + blockIdx.x;
        const int tid = threadIdx.y * 32 + threadIdx.x;
        const float4* xin = (const float4*)x;
        __half2* xout = (__half2*)XH;
#pragma unroll
        for (int i = 0; i < 4; ++i) {
            const int f4 = blk * 1024 + tid + i * 256;
            float4 v = xin[f4];
            xout[2 * f4 + 0] = __floats2half2_rn(v.x, v.y);
            xout[2 * f4 + 1] = __floats2half2_rn(v.z, v.w);
        }
    }
}

// ---------------------------------------------------------------------------
// fp16 mma.sync GEMM: C = A[m][k] @ WT[n][k]^T + bias.
// 128x128x64 tiles, 256 thr, 8 warps (64x32), 3-stage cp.async ring,
// ONE __syncthreads per k-chunk. Row pitch 144 B.
// smem: 3 stages x (A 18432 + B 18432) = 110592 B -> occupancy 2.
// ---------------------------------------------------------------------------
#define GSTAGE 36864
#define GEMM_SMEM (3 * GSTAGE)

template <bool STORE_HALF, typename OutT>
__device__ __forceinline__
void gemm_body(const __half* __restrict__ A, const __half* __restrict__ B,
               const float* __restrict__ bias, OutT* __restrict__ C) {
    extern __shared__ char smc[];
    const uint32_t smb = (uint32_t)__cvta_generic_to_shared(smc);
    const int tid  = threadIdx.x;
    const int lane = tid & 31;
    const int warp = tid >> 5;
    const int wr   = warp & 1;          // m 64*wr
    const int wc   = warp >> 1;         // n 32*wc
    const int m0   = blockIdx.y * 128;
    const int n0   = blockIdx.x * 128;

    const __half* Ab = A + (size_t)m0 * 1024;
    const __half* Bb = B + (size_t)n0 * 1024;

    const int mat = lane >> 3, lr = lane & 7;
    uint32_t aOff[4];
#pragma unroll
    for (int mt = 0; mt < 4; ++mt)
        aOff[mt] = (uint32_t)((wr * 64 + mt * 16 + (mat & 1) * 8 + lr) * 144 + (mat >> 1) * 16);
    uint32_t bOff[2];
#pragma unroll
    for (int p = 0; p < 2; ++p)
        bOff[p] = (uint32_t)((wc * 32 + p * 16 + (mat >> 1) * 8 + lr) * 144 + (mat & 1) * 16)
                  + 18432u;   // B half of each stage

    float acc[4][4][4];
#pragma unroll
    for (int mt = 0; mt < 4; ++mt)
#pragma unroll
        for (int nt = 0; nt < 4; ++nt)
#pragma unroll
            for (int i = 0; i < 4; ++i) acc[mt][nt][i] = 0.0f;

    const int srow = tid & 127;          // staged row
    const int sop  = tid >> 7;           // 0 = A, 1 = B
    auto stage = [&](int kc) {
        const uint32_t base = smb + (uint32_t)(kc % 3) * GSTAGE + (sop ? 18432u : 0u);
        const __half* g = (sop ? Bb : Ab) + (size_t)srow * 1024 + kc * 64;
        const uint32_t d = base + (uint32_t)srow * 144;
#pragma unroll
        for (int c = 0; c < 8; ++c)
            cp16(d + c * 16, g + c * 8);
    };

    stage(0);
    asm volatile("cp.async.commit_group;");
    stage(1);
    asm volatile("cp.async.commit_group;");

    const int NIT = 1024 / 64;  // 16
    for (int kc = 0; kc < NIT; ++kc) {
        if (kc + 1 < NIT) {
            asm volatile("cp.async.wait_group 1;");
        } else {
            asm volatile("cp.async.wait_group 0;");
        }
        __syncthreads();   // chunk kc visible to all; buf (kc-1)%3 free

        if (kc + 2 < NIT) {
            stage(kc + 2);
            asm volatile("cp.async.commit_group;");
        }

        const uint32_t sb = smb + (uint32_t)(kc % 3) * GSTAGE;
#pragma unroll
        for (int s = 0; s < 4; ++s) {
            const uint32_t kb = (uint32_t)(s * 32);
            uint32_t af[4][4], bf[2][4];
#pragma unroll
            for (int mt = 0; mt < 4; ++mt)
                ldsm4(af[mt][0], af[mt][1], af[mt][2], af[mt][3], sb + aOff[mt] + kb);
#pragma unroll
            for (int p = 0; p < 2; ++p)
                ldsm4(bf[p][0], bf[p][1], bf[p][2], bf[p][3], sb + bOff[p] + kb);
#pragma unroll
            for (int mt = 0; mt < 4; ++mt)
#pragma unroll
                for (int p = 0; p < 2; ++p) {
                    mma_f16(acc[mt][2 * p + 0], af[mt], bf[p][0], bf[p][1]);
                    mma_f16(acc[mt][2 * p + 1], af[mt], bf[p][2], bf[p][3]);
                }
        }
    }

    // epilogue
#pragma unroll
    for (int mt = 0; mt < 4; ++mt) {
        const int row = m0 + wr * 64 + mt * 16 + (lane >> 2);
#pragma unroll
        for (int nt = 0; nt < 4; ++nt) {
            const int col = n0 + wc * 32 + nt * 8 + 2 * (lane & 3);
            const float2 bia = *(const float2*)&bias[col];
            const float x0 = acc[mt][nt][0] + bia.x;
            const float y0 = acc[mt][nt][1] + bia.y;
            const float x1 = acc[mt][nt][2] + bia.x;
            const float y1 = acc[mt][nt][3] + bia.y;
            if (STORE_HALF) {
                __half2* Ch = (__half2*)C;
                Ch[((size_t)row * 1024 + col) >> 1]       = __floats2half2_rn(x0, y0);
                Ch[((size_t)(row + 8) * 1024 + col) >> 1] = __floats2half2_rn(x1, y1);
            } else {
                float* Cf = (float*)C;
                *(float2*)&Cf[(size_t)row * 1024 + col]       = make_float2(x0, y0);
                *(float2*)&Cf[(size_t)(row + 8) * 1024 + col] = make_float2(x1, y1);
            }
        }
    }
}

__global__ __launch_bounds__(256, 2)
void swa_gemm_qkv(const __half* __restrict__ xh, const __half* __restrict__ WT,
                  const float* __restrict__ bq, const float* __restrict__ bk,
                  const float* __restrict__ bv,
                  __half* __restrict__ Q, __half* __restrict__ K, __half* __restrict__ V) {
    const int z = blockIdx.z;
    const __half* W = WT + (size_t)z * D_MOD * D_MOD;
    const float* bias = (z == 0) ? bq : (z == 1) ? bk : bv;
    __half* C = (z == 0) ? Q : (z == 1) ? K : V;
    gemm_body<true>(xh, W, bias, C);
}

__global__ __launch_bounds__(256, 2)
void swa_gemm_o(const __half* __restrict__ A, const __half* __restrict__ WT,
                const float* __restrict__ bias, float* __restrict__ C) {
    gemm_body<false>(A, WT + (size_t)3 * D_MOD * D_MOD, bias, C);
}

// ---------------------------------------------------------------------------
// Attention v5 (fp16) — unchanged (R8).
// smem halves (pitch 144 B): Qs@0  Ks@9216B  Vs@18432B  Ps@27648B ; 36864 B.
// ---------------------------------------------------------------------------
#define A5_KS 9216
#define A5_VS 18432
#define A5_PS 27648
#define ATTN5_SMEM 36864

__global__ __launch_bounds__(128, 3)
void swa_attn5(const __half* __restrict__ Q, const __half* __restrict__ K,
               const __half* __restrict__ V, const float* __restrict__ beta,
               __half* __restrict__ O) {
    extern __shared__ char smc[];
    const uint32_t smb  = (uint32_t)__cvta_generic_to_shared(smc);
    __half* Ps = (__half*)(smc + A5_PS);

    const int z  = blockIdx.y;
    const int b  = z / H_NUM;
    const int h  = z % H_NUM;
    const int q0 = blockIdx.x * 64;
    const int tid  = threadIdx.x;
    const int lane = tid & 31;
    const int warp = tid >> 5;
    const int g   = lane >> 2;
    const int t4  = lane & 3;
    const int mat = lane >> 3, lr = lane & 7;

    const float scale = 1.0f / (8.0f * __expf(beta[h]));

#pragma unroll
    for (int it = 0; it < 4; ++it) {
        const int f = tid + it * 128;
        const int row = f >> 3, c = f & 7;
        cp16(smb + (uint32_t)(row * 144 + c * 16),
             Q + ((size_t)((q0 + row) * B_SZ + b)) * D_MOD + h * DH_SZ + c * 8);
    }
    asm volatile("cp.async.commit_group;");
    asm volatile("cp.async.wait_group 0;");
    __syncthreads();

    const uint32_t aRow = (uint32_t)((16 * warp + (mat & 1) * 8 + lr) * 144 + (mat >> 1) * 16);
    uint32_t qa[4][4];
#pragma unroll
    for (int s = 0; s < 4; ++s)
        ldsm4(qa[s][0], qa[s][1], qa[s][2], qa[s][3], smb + aRow + s * 32);

    uint32_t kOff[4];
#pragma unroll
    for (int p = 0; p < 4; ++p)
        kOff[p] = (uint32_t)((p * 16 + (mat >> 1) * 8 + lr) * 144 + (mat & 1) * 16);
    uint32_t vRowB[4];
#pragma unroll
    for (int s = 0; s < 4; ++s)
        vRowB[s] = (uint32_t)((s * 16 + (mat & 1) * 8 + lr) * 144 + (mat >> 1) * 16);

    float acc[8][4];
#pragma unroll
    for (int j = 0; j < 8; ++j)
#pragma unroll
        for (int i = 0; i < 4; ++i) acc[j][i] = 0.0f;

    const int r0  = 16 * warp + g;
    const int qr0 = q0 + r0;
    const int qr1 = qr0 + 8;
    float m0 = 0.0f, m1 = 0.0f, l0 = 1.0f, l1 = 1.0f;

    int kbeg = q0 - (WIN_SZ - 1);
    if (kbeg < 0) kbeg = 0;
    kbeg &= ~63;

    for (int t = kbeg; t < q0 + 64; t += 64) {
#pragma unroll
        for (int it = 0; it < 4; ++it) {
            const int f = tid + it * 128;
            const int row = f >> 3, c = f & 7;
            const size_t gofs = ((size_t)((t + row) * B_SZ + b)) * D_MOD + h * DH_SZ + c * 8;
            cp16(smb + A5_KS + (uint32_t)(row * 144 + c * 16), K + gofs);
            cp16(smb + A5_VS + (uint32_t)(row * 144 + c * 16), V + gofs);
        }
        asm volatile("cp.async.commit_group;");
        asm volatile("cp.async.wait_group 0;");
        __syncthreads();

        float c[8][4];
#pragma unroll
        for (int j = 0; j < 8; ++j)
#pragma unroll
            for (int i = 0; i < 4; ++i) c[j][i] = 0.0f;

#pragma unroll
        for (int s = 0; s < 4; ++s) {
            const uint32_t kb = (uint32_t)(s * 32);
#pragma unroll
            for (int p = 0; p < 4; ++p) {
                uint32_t b0, b1, b2, b3;
                ldsm4(b0, b1, b2, b3, smb + A5_KS + kOff[p] + kb);
                mma_f16(c[2 * p + 0], qa[s], b0, b1);
                mma_f16(c[2 * p + 1], qa[s], b2, b3);
            }
        }

#pragma unroll
        for (int j = 0; j < 8; ++j) {
            const int k0i = t + j * 8 + 2 * t4;
#pragma unroll
            for (int u = 0; u < 2; ++u) {
                const int kidx = k0i + u;
                const int d0q = qr0 - kidx;
                const int d1q = qr1 - kidx;
                c[j][u]     = (d0q >= 0 && d0q < WIN_SZ) ? c[j][u] * scale     : -1e30f;
                c[j][2 + u] = (d1q >= 0 && d1q < WIN_SZ) ? c[j][2 + u] * scale : -1e30f;
            }
        }

        float mx0 = m0, mx1 = m1;
#pragma unroll
        for (int j = 0; j < 8; ++j) {
            mx0 = fmaxf(mx0, fmaxf(c[j][0], c[j][1]));
            mx1 = fmaxf(mx1, fmaxf(c[j][2], c[j][3]));
        }
        mx0 = fmaxf(mx0, __shfl_xor_sync(0xffffffffu, mx0, 1));
        mx0 = fmaxf(mx0, __shfl_xor_sync(0xffffffffu, mx0, 2));
        mx1 = fmaxf(mx1, __shfl_xor_sync(0xffffffffu, mx1, 1));
        mx1 = fmaxf(mx1, __shfl_xor_sync(0xffffffffu, mx1, 2));

        const float fs0 = __expf(m0 - mx0);
        const float fs1 = __expf(m1 - mx1);
        float s0 = 0.0f, s1 = 0.0f;
#pragma unroll
        for (int j = 0; j < 8; ++j) {
            const float p0 = __expf(c[j][0] - mx0);
            const float p1 = __expf(c[j][1] - mx0);
            const float p2 = __expf(c[j][2] - mx1);
            const float p3 = __expf(c[j][3] - mx1);
            s0 += p0 + p1;
            s1 += p2 + p3;
            *(__half2*)&Ps[r0 * 72 + j * 8 + 2 * t4]       = __floats2half2_rn(p0, p1);
            *(__half2*)&Ps[(r0 + 8) * 72 + j * 8 + 2 * t4] = __floats2half2_rn(p2, p3);
        }
        s0 += __shfl_xor_sync(0xffffffffu, s0, 1);
        s0 += __shfl_xor_sync(0xffffffffu, s0, 2);
        s1 += __shfl_xor_sync(0xffffffffu, s1, 1);
        s1 += __shfl_xor_sync(0xffffffffu, s1, 2);

        l0 = l0 * fs0 + s0;
        l1 = l1 * fs1 + s1;
        m0 = mx0; m1 = mx1;

#pragma unroll
        for (int j = 0; j < 8; ++j) {
            acc[j][0] *= fs0; acc[j][1] *= fs0;
            acc[j][2] *= fs1; acc[j][3] *= fs1;
        }
        __syncwarp();

#pragma unroll
        for (int s = 0; s < 4; ++s) {
            uint32_t pa[4];
            ldsm4(pa[0], pa[1], pa[2], pa[3], smb + A5_PS + aRow + s * 32);
#pragma unroll
            for (int p = 0; p < 4; ++p) {
                uint32_t v0, v1, v2, v3;
                ldsm4t(v0, v1, v2, v3, smb + A5_VS + vRowB[s] + p * 32);
                mma_f16(acc[2 * p + 0], pa, v0, v1);
                mma_f16(acc[2 * p + 1], pa, v2, v3);
            }
        }
        __syncthreads();
    }

    const float rl0 = 1.0f / l0;
    const float rl1 = 1.0f / l1;
#pragma unroll
    for (int j = 0; j < 8; ++j) {
        const int col = h * DH_SZ + j * 8 + 2 * t4;
        *(__half2*)&O[((size_t)(qr0 * B_SZ + b)) * D_MOD + col] =
            __floats2half2_rn(acc[j][0] * rl0, acc[j][1] * rl0);
        *(__half2*)&O[((size_t)(qr1 * B_SZ + b)) * D_MOD + col] =
            __floats2half2_rn(acc[j][2] * rl1, acc[j][3] * rl1);
    }
}

// ---------------------------------------------------------------------------
extern "C" void kernel_launch(void* const* d_in, const int* in_sizes, int n_in,
                              void* d_out, int out_size) {
    const float* x    = (const float*)d_in[0];
    const float* beta = (const float*)d_in[1];
    const float* Wq   = (const float*)d_in[2];
    const float* bq   = (const float*)d_in[3];
    const float* Wk   = (const float*)d_in[4];
    const float* bk   = (const float*)d_in[5];
    const float* Wv   = (const float*)d_in[6];
    const float* bv   = (const float*)d_in[7];
    const float* Wo   = (const float*)d_in[8];
    const float* bo   = (const float*)d_in[9];
    float* out = (float*)d_out;

    __half *XH, *WTH, *Qh, *Kh, *Vh, *Oh;
    cudaGetSymbolAddress((void**)&XH,  g_h_X);
    cudaGetSymbolAddress((void**)&WTH, g_h_WT);
    cudaGetSymbolAddress((void**)&Qh,  g_h_Q);
    cudaGetSymbolAddress((void**)&Kh,  g_h_K);
    cudaGetSymbolAddress((void**)&Vh,  g_h_V);
    cudaGetSymbolAddress((void**)&Oh,  g_h_O);

    cudaFuncSetAttribute(swa_attn5, cudaFuncAttributeMaxDynamicSharedMemorySize,
                         ATTN5_SMEM);
    cudaFuncSetAttribute(swa_gemm_qkv, cudaFuncAttributeMaxDynamicSharedMemorySize,
                         GEMM_SMEM);
    cudaFuncSetAttribute(swa_gemm_o, cudaFuncAttributeMaxDynamicSharedMemorySize,
                         GEMM_SMEM);

    swa_prep<<<dim3(32, 32, 5), dim3(32, 8)>>>(x, Wq, Wk, Wv, Wo, XH, WTH);

    dim3 qkvgrid(D_MOD / 128, M_ROWS / 128, 3);   // (8, 32, 3)
    swa_gemm_qkv<<<qkvgrid, 256, GEMM_SMEM>>>(XH, WTH, bq, bk, bv, Qh, Kh, Vh);

    dim3 agrid(S_LEN / 64, B_SZ * H_NUM);         // (32, 32)
    swa_attn5<<<agrid, 128, ATTN5_SMEM>>>(Qh, Kh, Vh, beta, Oh);

    dim3 ogrid(D_MOD / 128, M_ROWS / 128);        // (8, 32)
    swa_gemm_o<<<ogrid, 256, GEMM_SMEM>>>(Oh, WTH, bo, out);
}

// round 15
// speedup vs baseline: 1.5097x; 1.5092x over previous
#include <cuda_runtime.h>
#include <cuda_fp16.h>
#include <cstdint>

#define S_LEN 2048
#define B_SZ  2
#define D_MOD 1024
#define H_NUM 16
#define DH_SZ 64
#define WIN_SZ 256
#define M_ROWS (S_LEN * B_SZ)   // 4096

// Scratch (device globals — no allocation allowed)
__device__ __half g_h_X[M_ROWS * D_MOD];         // fp16 x
__device__ __half g_h_WT[4 * D_MOD * D_MOD];     // fp16 W^T (q,k,v,o) [n][k]
__device__ __half g_h_Q[M_ROWS * D_MOD];
__device__ __half g_h_K[M_ROWS * D_MOD];
__device__ __half g_h_V[M_ROWS * D_MOD];
__device__ __half g_h_O[M_ROWS * D_MOD];

// ---------------------------------------------------------------------------
__device__ __forceinline__ void cp16(uint32_t dst_smem, const void* src) {
    asm volatile("cp.async.cg.shared.global [%0], [%1], 16;"
                 :: "r"(dst_smem), "l"(src));
}
__device__ __forceinline__ void ldsm4(uint32_t& r0, uint32_t& r1, uint32_t& r2,
                                      uint32_t& r3, uint32_t addr) {
    asm volatile("ldmatrix.sync.aligned.m8n8.x4.shared.b16 {%0,%1,%2,%3}, [%4];"
                 : "=r"(r0), "=r"(r1), "=r"(r2), "=r"(r3) : "r"(addr));
}
__device__ __forceinline__ void ldsm4t(uint32_t& r0, uint32_t& r1, uint32_t& r2,
                                       uint32_t& r3, uint32_t addr) {
    asm volatile("ldmatrix.sync.aligned.m8n8.x4.trans.shared.b16 {%0,%1,%2,%3}, [%4];"
                 : "=r"(r0), "=r"(r1), "=r"(r2), "=r"(r3) : "r"(addr));
}
__device__ __forceinline__ void mma_f16(float c[4], const uint32_t a[4],
                                        const uint32_t b0, const uint32_t b1) {
    asm volatile(
        "mma.sync.aligned.m16n8k16.row.col.f32.f16.f16.f32 "
        "{%0,%1,%2,%3}, {%4,%5,%6,%7}, {%8,%9}, {%0,%1,%2,%3};"
        : "+f"(c[0]), "+f"(c[1]), "+f"(c[2]), "+f"(c[3])
        : "r"(a[0]), "r"(a[1]), "r"(a[2]), "r"(a[3]), "r"(b0), "r"(b1));
}

// ---------------------------------------------------------------------------
// merged pre-pass: z<4 -> transpose+round W_z into WT[n][k]; z==4 -> round x
// ---------------------------------------------------------------------------
__global__ void swa_prep(const float* __restrict__ x,
                         const float* __restrict__ Wq, const float* __restrict__ Wk,
                         const float* __restrict__ Wv, const float* __restrict__ Wo,
                         __half* __restrict__ XH, __half* __restrict__ WT) {
    const int z = blockIdx.z;
    if (z < 4) {
        __shared__ float t[32][33];
        const float* W = (z == 0) ? Wq : (z == 1) ? Wk : (z == 2) ? Wv : Wo;
        __half* Dst = WT + (size_t)z * D_MOD * D_MOD;
        const int n0 = blockIdx.x * 32, k0 = blockIdx.y * 32;
#pragma unroll
        for (int i = threadIdx.y; i < 32; i += 8)
            t[i][threadIdx.x] = W[(size_t)(k0 + i) * D_MOD + n0 + threadIdx.x];
        __syncthreads();
#pragma unroll
        for (int i = threadIdx.y; i < 32; i += 8)
            Dst[(size_t)(n0 + i) * D_MOD + k0 + threadIdx.x] =
                __float2half_rn(t[threadIdx.x][i]);
    } else {
        const int blk = blockIdx.y * 32 + blockIdx.x;
        const int tid = threadIdx.y * 32 + threadIdx.x;
        const float4* xin = (const float4*)x;
        __half2* xout = (__half2*)XH;
#pragma unroll
        for (int i = 0; i < 4; ++i) {
            const int f4 = blk * 1024 + tid + i * 256;
            float4 v = xin[f4];
            xout[2 * f4 + 0] = __floats2half2_rn(v.x, v.y);
            xout[2 * f4 + 1] = __floats2half2_rn(v.z, v.w);
        }
    }
}

// ---------------------------------------------------------------------------
// fp16 mma.sync GEMM: C = A[m][k] @ WT[n][k]^T + bias.
// 128x128x64 tiles, 256 thr, 8 warps (64x32), 3-stage cp.async ring,
// ONE __syncthreads per k-chunk. Row pitch 144 B.
// Staging is sector-coalesced: each LDGSTS instruction covers 4 rows x 128
// contiguous bytes (16 full 32B sectors), instead of 32 rows x 16B.
// smem: 3 stages x (A 18432 + B 18432) = 110592 B -> occupancy 2.
// ---------------------------------------------------------------------------
#define GSTAGE 36864
#define GEMM_SMEM (3 * GSTAGE)

template <bool STORE_HALF, typename OutT>
__device__ __forceinline__
void gemm_body(const __half* __restrict__ A, const __half* __restrict__ B,
               const float* __restrict__ bias, OutT* __restrict__ C) {
    extern __shared__ char smc[];
    const uint32_t smb = (uint32_t)__cvta_generic_to_shared(smc);
    const int tid  = threadIdx.x;
    const int lane = tid & 31;
    const int warp = tid >> 5;
    const int wr   = warp & 1;          // m 64*wr
    const int wc   = warp >> 1;         // n 32*wc
    const int m0   = blockIdx.y * 128;
    const int n0   = blockIdx.x * 128;

    const __half* Ab = A + (size_t)m0 * 1024;
    const __half* Bb = B + (size_t)n0 * 1024;

    const int mat = lane >> 3, lr = lane & 7;
    uint32_t aOff[4];
#pragma unroll
    for (int mt = 0; mt < 4; ++mt)
        aOff[mt] = (uint32_t)((wr * 64 + mt * 16 + (mat & 1) * 8 + lr) * 144 + (mat >> 1) * 16);
    uint32_t bOff[2];
#pragma unroll
    for (int p = 0; p < 2; ++p)
        bOff[p] = (uint32_t)((wc * 32 + p * 16 + (mat >> 1) * 8 + lr) * 144 + (mat & 1) * 16)
                  + 18432u;   // B half of each stage

    float acc[4][4][4];
#pragma unroll
    for (int mt = 0; mt < 4; ++mt)
#pragma unroll
        for (int nt = 0; nt < 4; ++nt)
#pragma unroll
            for (int i = 0; i < 4; ++i) acc[mt][nt][i] = 0.0f;

    // Coalesced staging: r0 = tid>>3 (8 lanes per row), c = tid&7 (16B col).
    // Per LDGSTS instruction: 4 rows x 128 contiguous bytes.
    const int srow = tid >> 3;           // 0..31
    const int scol = tid & 7;            // 0..7
    auto stage = [&](int kc) {
        const uint32_t base = smb + (uint32_t)(kc % 3) * GSTAGE;
        const int kg = kc * 64 + scol * 8;
#pragma unroll
        for (int i = 0; i < 4; ++i) {
            const int row = srow + i * 32;
            cp16(base + (uint32_t)(row * 144 + scol * 16),
                 Ab + (size_t)row * 1024 + kg);
        }
#pragma unroll
        for (int i = 0; i < 4; ++i) {
            const int row = srow + i * 32;
            cp16(base + 18432u + (uint32_t)(row * 144 + scol * 16),
                 Bb + (size_t)row * 1024 + kg);
        }
    };

    stage(0);
    asm volatile("cp.async.commit_group;");
    stage(1);
    asm volatile("cp.async.commit_group;");

    const int NIT = 1024 / 64;  // 16
    for (int kc = 0; kc < NIT; ++kc) {
        if (kc + 1 < NIT) {
            asm volatile("cp.async.wait_group 1;");
        } else {
            asm volatile("cp.async.wait_group 0;");
        }
        __syncthreads();   // chunk kc visible to all; buf (kc-1)%3 free

        if (kc + 2 < NIT) {
            stage(kc + 2);
            asm volatile("cp.async.commit_group;");
        }

        const uint32_t sb = smb + (uint32_t)(kc % 3) * GSTAGE;
#pragma unroll
        for (int s = 0; s < 4; ++s) {
            const uint32_t kb = (uint32_t)(s * 32);
            uint32_t af[4][4], bf[2][4];
#pragma unroll
            for (int mt = 0; mt < 4; ++mt)
                ldsm4(af[mt][0], af[mt][1], af[mt][2], af[mt][3], sb + aOff[mt] + kb);
#pragma unroll
            for (int p = 0; p < 2; ++p)
                ldsm4(bf[p][0], bf[p][1], bf[p][2], bf[p][3], sb + bOff[p] + kb);
#pragma unroll
            for (int mt = 0; mt < 4; ++mt)
#pragma unroll
                for (int p = 0; p < 2; ++p) {
                    mma_f16(acc[mt][2 * p + 0], af[mt], bf[p][0], bf[p][1]);
                    mma_f16(acc[mt][2 * p + 1], af[mt], bf[p][2], bf[p][3]);
                }
        }
    }

    // epilogue
#pragma unroll
    for (int mt = 0; mt < 4; ++mt) {
        const int row = m0 + wr * 64 + mt * 16 + (lane >> 2);
#pragma unroll
        for (int nt = 0; nt < 4; ++nt) {
            const int col = n0 + wc * 32 + nt * 8 + 2 * (lane & 3);
            const float2 bia = *(const float2*)&bias[col];
            const float x0 = acc[mt][nt][0] + bia.x;
            const float y0 = acc[mt][nt][1] + bia.y;
            const float x1 = acc[mt][nt][2] + bia.x;
            const float y1 = acc[mt][nt][3] + bia.y;
            if (STORE_HALF) {
                __half2* Ch = (__half2*)C;
                Ch[((size_t)row * 1024 + col) >> 1]       = __floats2half2_rn(x0, y0);
                Ch[((size_t)(row + 8) * 1024 + col) >> 1] = __floats2half2_rn(x1, y1);
            } else {
                float* Cf = (float*)C;
                *(float2*)&Cf[(size_t)row * 1024 + col]       = make_float2(x0, y0);
                *(float2*)&Cf[(size_t)(row + 8) * 1024 + col] = make_float2(x1, y1);
            }
        }
    }
}

__global__ __launch_bounds__(256, 2)
void swa_gemm_qkv(const __half* __restrict__ xh, const __half* __restrict__ WT,
                  const float* __restrict__ bq, const float* __restrict__ bk,
                  const float* __restrict__ bv,
                  __half* __restrict__ Q, __half* __restrict__ K, __half* __restrict__ V) {
    const int z = blockIdx.z;
    const __half* W = WT + (size_t)z * D_MOD * D_MOD;
    const float* bias = (z == 0) ? bq : (z == 1) ? bk : bv;
    __half* C = (z == 0) ? Q : (z == 1) ? K : V;
    gemm_body<true>(xh, W, bias, C);
}

__global__ __launch_bounds__(256, 2)
void swa_gemm_o(const __half* __restrict__ A, const __half* __restrict__ WT,
                const float* __restrict__ bias, float* __restrict__ C) {
    gemm_body<false>(A, WT + (size_t)3 * D_MOD * D_MOD, bias, C);
}

// ---------------------------------------------------------------------------
// Attention v5 (fp16) — unchanged (R8 best).
// smem halves (pitch 144 B): Qs@0  Ks@9216B  Vs@18432B  Ps@27648B ; 36864 B.
// ---------------------------------------------------------------------------
#define A5_KS 9216
#define A5_VS 18432
#define A5_PS 27648
#define ATTN5_SMEM 36864

__global__ __launch_bounds__(128, 3)
void swa_attn5(const __half* __restrict__ Q, const __half* __restrict__ K,
               const __half* __restrict__ V, const float* __restrict__ beta,
               __half* __restrict__ O) {
    extern __shared__ char smc[];
    const uint32_t smb  = (uint32_t)__cvta_generic_to_shared(smc);
    __half* Ps = (__half*)(smc + A5_PS);

    const int z  = blockIdx.y;
    const int b  = z / H_NUM;
    const int h  = z % H_NUM;
    const int q0 = blockIdx.x * 64;
    const int tid  = threadIdx.x;
    const int lane = tid & 31;
    const int warp = tid >> 5;
    const int g   = lane >> 2;
    const int t4  = lane & 3;
    const int mat = lane >> 3, lr = lane & 7;

    const float scale = 1.0f / (8.0f * __expf(beta[h]));

#pragma unroll
    for (int it = 0; it < 4; ++it) {
        const int f = tid + it * 128;
        const int row = f >> 3, c = f & 7;
        cp16(smb + (uint32_t)(row * 144 + c * 16),
             Q + ((size_t)((q0 + row) * B_SZ + b)) * D_MOD + h * DH_SZ + c * 8);
    }
    asm volatile("cp.async.commit_group;");
    asm volatile("cp.async.wait_group 0;");
    __syncthreads();

    const uint32_t aRow = (uint32_t)((16 * warp + (mat & 1) * 8 + lr) * 144 + (mat >> 1) * 16);
    uint32_t qa[4][4];
#pragma unroll
    for (int s = 0; s < 4; ++s)
        ldsm4(qa[s][0], qa[s][1], qa[s][2], qa[s][3], smb + aRow + s * 32);

    uint32_t kOff[4];
#pragma unroll
    for (int p = 0; p < 4; ++p)
        kOff[p] = (uint32_t)((p * 16 + (mat >> 1) * 8 + lr) * 144 + (mat & 1) * 16);
    uint32_t vRowB[4];
#pragma unroll
    for (int s = 0; s < 4; ++s)
        vRowB[s] = (uint32_t)((s * 16 + (mat & 1) * 8 + lr) * 144 + (mat >> 1) * 16);

    float acc[8][4];
#pragma unroll
    for (int j = 0; j < 8; ++j)
#pragma unroll
        for (int i = 0; i < 4; ++i) acc[j][i] = 0.0f;

    const int r0  = 16 * warp + g;
    const int qr0 = q0 + r0;
    const int qr1 = qr0 + 8;
    float m0 = 0.0f, m1 = 0.0f, l0 = 1.0f, l1 = 1.0f;

    int kbeg = q0 - (WIN_SZ - 1);
    if (kbeg < 0) kbeg = 0;
    kbeg &= ~63;

    for (int t = kbeg; t < q0 + 64; t += 64) {
#pragma unroll
        for (int it = 0; it < 4; ++it) {
            const int f = tid + it * 128;
            const int row = f >> 3, c = f & 7;
            const size_t gofs = ((size_t)((t + row) * B_SZ + b)) * D_MOD + h * DH_SZ + c * 8;
            cp16(smb + A5_KS + (uint32_t)(row * 144 + c * 16), K + gofs);
            cp16(smb + A5_VS + (uint32_t)(row * 144 + c * 16), V + gofs);
        }
        asm volatile("cp.async.commit_group;");
        asm volatile("cp.async.wait_group 0;");
        __syncthreads();

        float c[8][4];
#pragma unroll
        for (int j = 0; j < 8; ++j)
#pragma unroll
            for (int i = 0; i < 4; ++i) c[j][i] = 0.0f;

#pragma unroll
        for (int s = 0; s < 4; ++s) {
            const uint32_t kb = (uint32_t)(s * 32);
#pragma unroll
            for (int p = 0; p < 4; ++p) {
                uint32_t b0, b1, b2, b3;
                ldsm4(b0, b1, b2, b3, smb + A5_KS + kOff[p] + kb);
                mma_f16(c[2 * p + 0], qa[s], b0, b1);
                mma_f16(c[2 * p + 1], qa[s], b2, b3);
            }
        }

#pragma unroll
        for (int j = 0; j < 8; ++j) {
            const int k0i = t + j * 8 + 2 * t4;
#pragma unroll
            for (int u = 0; u < 2; ++u) {
                const int kidx = k0i + u;
                const int d0q = qr0 - kidx;
                const int d1q = qr1 - kidx;
                c[j][u]     = (d0q >= 0 && d0q < WIN_SZ) ? c[j][u] * scale     : -1e30f;
                c[j][2 + u] = (d1q >= 0 && d1q < WIN_SZ) ? c[j][2 + u] * scale : -1e30f;
            }
        }

        float mx0 = m0, mx1 = m1;
#pragma unroll
        for (int j = 0; j < 8; ++j) {
            mx0 = fmaxf(mx0, fmaxf(c[j][0], c[j][1]));
            mx1 = fmaxf(mx1, fmaxf(c[j][2], c[j][3]));
        }
        mx0 = fmaxf(mx0, __shfl_xor_sync(0xffffffffu, mx0, 1));
        mx0 = fmaxf(mx0, __shfl_xor_sync(0xffffffffu, mx0, 2));
        mx1 = fmaxf(mx1, __shfl_xor_sync(0xffffffffu, mx1, 1));
        mx1 = fmaxf(mx1, __shfl_xor_sync(0xffffffffu, mx1, 2));

        const float fs0 = __expf(m0 - mx0);
        const float fs1 = __expf(m1 - mx1);
        float s0 = 0.0f, s1 = 0.0f;
#pragma unroll
        for (int j = 0; j < 8; ++j) {
            const float p0 = __expf(c[j][0] - mx0);
            const float p1 = __expf(c[j][1] - mx0);
            const float p2 = __expf(c[j][2] - mx1);
            const float p3 = __expf(c[j][3] - mx1);
            s0 += p0 + p1;
            s1 += p2 + p3;
            *(__half2*)&Ps[r0 * 72 + j * 8 + 2 * t4]       = __floats2half2_rn(p0, p1);
            *(__half2*)&Ps[(r0 + 8) * 72 + j * 8 + 2 * t4] = __floats2half2_rn(p2, p3);
        }
        s0 += __shfl_xor_sync(0xffffffffu, s0, 1);
        s0 += __shfl_xor_sync(0xffffffffu, s0, 2);
        s1 += __shfl_xor_sync(0xffffffffu, s1, 1);
        s1 += __shfl_xor_sync(0xffffffffu, s1, 2);

        l0 = l0 * fs0 + s0;
        l1 = l1 * fs1 + s1;
        m0 = mx0; m1 = mx1;

#pragma unroll
        for (int j = 0; j < 8; ++j) {
            acc[j][0] *= fs0; acc[j][1] *= fs0;
            acc[j][2] *= fs1; acc[j][3] *= fs1;
        }
        __syncwarp();

#pragma unroll
        for (int s = 0; s < 4; ++s) {
            uint32_t pa[4];
            ldsm4(pa[0], pa[1], pa[2], pa[3], smb + A5_PS + aRow + s * 32);
#pragma unroll
            for (int p = 0; p < 4; ++p) {
                uint32_t v0, v1, v2, v3;
                ldsm4t(v0, v1, v2, v3, smb + A5_VS + vRowB[s] + p * 32);
                mma_f16(acc[2 * p + 0], pa, v0, v1);
                mma_f16(acc[2 * p + 1], pa, v2, v3);
            }
        }
        __syncthreads();
    }

    const float rl0 = 1.0f / l0;
    const float rl1 = 1.0f / l1;
#pragma unroll
    for (int j = 0; j < 8; ++j) {
        const int col = h * DH_SZ + j * 8 + 2 * t4;
        *(__half2*)&O[((size_t)(qr0 * B_SZ + b)) * D_MOD + col] =
            __floats2half2_rn(acc[j][0] * rl0, acc[j][1] * rl0);
        *(__half2*)&O[((size_t)(qr1 * B_SZ + b)) * D_MOD + col] =
            __floats2half2_rn(acc[j][2] * rl1, acc[j][3] * rl1);
    }
}

// ---------------------------------------------------------------------------
extern "C" void kernel_launch(void* const* d_in, const int* in_sizes, int n_in,
                              void* d_out, int out_size) {
    const float* x    = (const float*)d_in[0];
    const float* beta = (const float*)d_in[1];
    const float* Wq   = (const float*)d_in[2];
    const float* bq   = (const float*)d_in[3];
    const float* Wk   = (const float*)d_in[4];
    const float* bk   = (const float*)d_in[5];
    const float* Wv   = (const float*)d_in[6];
    const float* bv   = (const float*)d_in[7];
    const float* Wo   = (const float*)d_in[8];
    const float* bo   = (const float*)d_in[9];
    float* out = (float*)d_out;

    __half *XH, *WTH, *Qh, *Kh, *Vh, *Oh;
    cudaGetSymbolAddress((void**)&XH,  g_h_X);
    cudaGetSymbolAddress((void**)&WTH, g_h_WT);
    cudaGetSymbolAddress((void**)&Qh,  g_h_Q);
    cudaGetSymbolAddress((void**)&Kh,  g_h_K);
    cudaGetSymbolAddress((void**)&Vh,  g_h_V);
    cudaGetSymbolAddress((void**)&Oh,  g_h_O);

    cudaFuncSetAttribute(swa_attn5, cudaFuncAttributeMaxDynamicSharedMemorySize,
                         ATTN5_SMEM);
    cudaFuncSetAttribute(swa_gemm_qkv, cudaFuncAttributeMaxDynamicSharedMemorySize,
                         GEMM_SMEM);
    cudaFuncSetAttribute(swa_gemm_o, cudaFuncAttributeMaxDynamicSharedMemorySize,
                         GEMM_SMEM);

    swa_prep<<<dim3(32, 32, 5), dim3(32, 8)>>>(x, Wq, Wk, Wv, Wo, XH, WTH);

    dim3 qkvgrid(D_MOD / 128, M_ROWS / 128, 3);   // (8, 32, 3)
    swa_gemm_qkv<<<qkvgrid, 256, GEMM_SMEM>>>(XH, WTH, bq, bk, bv, Qh, Kh, Vh);

    dim3 agrid(S_LEN / 64, B_SZ * H_NUM);         // (32, 32)
    swa_attn5<<<agrid, 128, ATTN5_SMEM>>>(Qh, Kh, Vh, beta, Oh);

    dim3 ogrid(D_MOD / 128, M_ROWS / 128);        // (8, 32)
    swa_gemm_o<<<ogrid, 256, GEMM_SMEM>>>(Oh, WTH, bo, out);
}